// round 2
// baseline (speedup 1.0000x reference)
#include <cuda_runtime.h>

typedef unsigned long long u64;

#define SEQ   20
#define FEAT  5
#define NU1   10
#define NU2   7
#define NU3   4
#define NOUT  4
#define NBATCH 262144
#define NTHREADS 128

// ---------------- packed f32x2 helpers (u64 = f32x2 register pair) ----------------
__device__ __forceinline__ u64 pack2(float lo, float hi) {
    u64 r; asm("mov.b64 %0, {%1, %2};" : "=l"(r) : "f"(lo), "f"(hi)); return r;
}
__device__ __forceinline__ u64 dup2(float s) {
    u64 r; asm("mov.b64 %0, {%1, %1};" : "=l"(r) : "f"(s)); return r;
}
__device__ __forceinline__ void unpack2(u64 v, float& lo, float& hi) {
    asm("mov.b64 {%0, %1}, %2;" : "=f"(lo), "=f"(hi) : "l"(v));
}
__device__ __forceinline__ u64 ffma2(u64 a, u64 b, u64 c) {
    u64 d; asm("fma.rn.f32x2 %0, %1, %2, %3;" : "=l"(d) : "l"(a), "l"(b), "l"(c)); return d;
}
__device__ __forceinline__ u64 fmul2(u64 a, u64 b) {
    u64 d; asm("mul.rn.f32x2 %0, %1, %2;" : "=l"(d) : "l"(a), "l"(b)); return d;
}

// ---------------- accurate-enough nonlinearities (2 MUFU each) ----------------
__device__ __forceinline__ float fast_ex2(float x) {
    float y; asm("ex2.approx.f32 %0, %1;" : "=f"(y) : "f"(x)); return y;
}
__device__ __forceinline__ float fast_rcp(float x) {
    float y; asm("rcp.approx.f32 %0, %1;" : "=f"(y) : "f"(x)); return y;
}
__device__ __forceinline__ float sigmoid1(float x) {
    return fast_rcp(1.0f + fast_ex2(-1.4426950408889634f * x));
}
__device__ __forceinline__ float tanh1(float x) {
    return fmaf(-2.0f, fast_rcp(1.0f + fast_ex2(2.8853900817779268f * x)), 1.0f);
}
__device__ __forceinline__ u64 sigmoid2(u64 v) {
    float a, b; unpack2(v, a, b);
    return pack2(sigmoid1(a), sigmoid1(b));
}
__device__ __forceinline__ u64 tanh2(u64 v) {
    float a, b; unpack2(v, a, b);
    return pack2(tanh1(a), tanh1(b));
}

// ---------------- shared-memory layout (floats) ----------------
// Combined weight per layer: rows = D (Wk rows) then U (Wr rows).
// Per row: PH unit-pairs x 4 gates, each gate a packed f32 pair.
// u64 index within layer = (row*PH + p)*4 + g ; floats = 2x that.
constexpr int OFF_W1 = 0;      // 15 rows * 5 PH * 4 g * 2 = 600
constexpr int OFF_B1 = 600;    // 5*4*2 = 40
constexpr int OFF_W2 = 640;    // 17 rows * 4 PH * 4 g * 2 = 544   (U2 padded 7->8)
constexpr int OFF_B2 = 1184;   // 4*4*2 = 32
constexpr int OFF_W3 = 1216;   // 11 rows * 2 PH * 4 g * 2 = 176
constexpr int OFF_B3 = 1392;   // 2*4*2 = 16
constexpr int OFF_WD = 1408;   // 4 rows * 2 pairs * 2 = 16
constexpr int OFF_BD = 1424;   // 4
constexpr int SMEM_FLOATS = 1428;  // 5712 B

__device__ __forceinline__ void load_wcomb(float* dst, const float* __restrict__ Wk,
                                           const float* __restrict__ Wr,
                                           int D, int U, int PH) {
    int total = (D + U) * PH * 4;
    for (int idx = threadIdx.x; idx < total; idx += blockDim.x) {
        int row = idx / (PH * 4);
        int rem = idx - row * (PH * 4);
        int p = rem >> 2, g = rem & 3;
        const float* src = (row < D) ? (Wk + row * 4 * U) : (Wr + (row - D) * 4 * U);
        int u0 = 2 * p, u1 = u0 + 1;
        dst[2 * idx]     = (u0 < U) ? src[g * U + u0] : 0.0f;
        dst[2 * idx + 1] = (u1 < U) ? src[g * U + u1] : 0.0f;
    }
}
__device__ __forceinline__ void load_bias(float* dst, const float* __restrict__ b,
                                          int U, int PH) {
    int total = PH * 4;
    for (int idx = threadIdx.x; idx < total; idx += blockDim.x) {
        int p = idx >> 2, g = idx & 3;
        int u0 = 2 * p, u1 = u0 + 1;
        dst[2 * idx]     = (u0 < U) ? b[g * U + u0] : 0.0f;
        dst[2 * idx + 1] = (u1 < U) ? b[g * U + u1] : 0.0f;
    }
}

// ---------------- one LSTM layer step (pair-packed units) ----------------
// mult[k] : broadcast-duplicated f32x2 of input scalar k (x features then old h)
// h, c    : PH packed unit-pairs
template<int NROWS, int PH>
__device__ __forceinline__ void layer_step(const u64* __restrict__ mult, u64* h, u64* c,
                                           const float* __restrict__ w,
                                           const float* __restrict__ bias) {
#pragma unroll
    for (int p = 0; p < PH; p++) {
        ulonglong2 bv0 = *(const ulonglong2*)(bias + p * 8);
        ulonglong2 bv1 = *(const ulonglong2*)(bias + p * 8 + 4);
        u64 za = bv0.x, zf = bv0.y, zg = bv1.x, zo = bv1.y;
#pragma unroll
        for (int k = 0; k < NROWS; k++) {
            const float* row = w + (k * PH + p) * 8;
            ulonglong2 w0 = *(const ulonglong2*)(row);
            ulonglong2 w1 = *(const ulonglong2*)(row + 4);
            u64 m = mult[k];
            za = ffma2(m, w0.x, za);
            zf = ffma2(m, w0.y, zf);
            zg = ffma2(m, w1.x, zg);
            zo = ffma2(m, w1.y, zo);
        }
        u64 iv = sigmoid2(za), fv = sigmoid2(zf), gv = tanh2(zg), ov = sigmoid2(zo);
        u64 cn = ffma2(fv, c[p], fmul2(iv, gv));
        c[p] = cn;
        h[p] = fmul2(ov, tanh2(cn));
    }
}

template<int NP>
__device__ __forceinline__ void dup_from_pairs(u64* dst, const u64* h) {
#pragma unroll
    for (int j = 0; j < NP; j++) {
        float a, b; unpack2(h[j], a, b);
        dst[2 * j]     = dup2(a);
        dst[2 * j + 1] = dup2(b);
    }
}

// ---------------- transpose scratch: x [B][T*F] -> xT [T*F][B] ----------------
__device__ float g_xT[(size_t)NBATCH * SEQ * FEAT];

__global__ void __launch_bounds__(1024)
transpose_kernel(const float* __restrict__ x) {
    __shared__ float tile[32][33];
    int c0 = blockIdx.x * 32;           // column within [0,100)
    int b0 = blockIdx.y * 32;           // batch base
    int col = c0 + threadIdx.x;
    int b   = b0 + threadIdx.y;
    if (col < SEQ * FEAT)
        tile[threadIdx.y][threadIdx.x] = x[(size_t)b * (SEQ * FEAT) + col];
    __syncthreads();
    int ocol = c0 + threadIdx.y;
    int ob   = b0 + threadIdx.x;
    if (ocol < SEQ * FEAT)
        g_xT[(size_t)ocol * NBATCH + ob] = tile[threadIdx.x][threadIdx.y];
}

// ---------------- fused 3-layer LSTM + dense + sigmoid ----------------
__global__ void __launch_bounds__(NTHREADS, 3)
lstm3_kernel(const float* __restrict__ Wk1, const float* __restrict__ Wr1, const float* __restrict__ b1,
             const float* __restrict__ Wk2, const float* __restrict__ Wr2, const float* __restrict__ b2,
             const float* __restrict__ Wk3, const float* __restrict__ Wr3, const float* __restrict__ b3,
             const float* __restrict__ Wd,  const float* __restrict__ bd,
             float* __restrict__ out) {
    __shared__ __align__(16) float s[SMEM_FLOATS];
    load_wcomb(s + OFF_W1, Wk1, Wr1, FEAT, NU1, 5);
    load_bias (s + OFF_B1, b1, NU1, 5);
    load_wcomb(s + OFF_W2, Wk2, Wr2, NU1, NU2, 4);   // padded to 8 units
    load_bias (s + OFF_B2, b2, NU2, 4);
    load_wcomb(s + OFF_W3, Wk3, Wr3, NU2, NU3, 2);
    load_bias (s + OFF_B3, b3, NU3, 2);
    // dense: Wd [4][4] -> pairs ; bd -> 2 pairs
    for (int idx = threadIdx.x; idx < 8; idx += blockDim.x) {
        int k = idx >> 1, p = idx & 1;
        s[OFF_WD + 2 * idx]     = Wd[k * 4 + 2 * p];
        s[OFF_WD + 2 * idx + 1] = Wd[k * 4 + 2 * p + 1];
    }
    for (int idx = threadIdx.x; idx < 4; idx += blockDim.x)
        s[OFF_BD + idx] = bd[idx];
    __syncthreads();

    int gid = blockIdx.x * NTHREADS + threadIdx.x;
    float* op = out + (size_t)gid * (SEQ * NOUT);

    u64 h1[5], c1[5], h2[4], c2[4], h3[2], c3[2];
#pragma unroll
    for (int i = 0; i < 5; i++) { h1[i] = 0ull; c1[i] = 0ull; }
#pragma unroll
    for (int i = 0; i < 4; i++) { h2[i] = 0ull; c2[i] = 0ull; }
#pragma unroll
    for (int i = 0; i < 2; i++) { h3[i] = 0ull; c3[i] = 0ull; }

#pragma unroll 1
    for (int t = 0; t < SEQ; t++) {
        // ---- layer 1 : D=5, U=10 (5 pairs), rows = 15 ----
        u64 m1[15];
#pragma unroll
        for (int k = 0; k < FEAT; k++)
            m1[k] = dup2(__ldg(&g_xT[(size_t)(t * FEAT + k) * NBATCH + gid]));
        dup_from_pairs<5>(m1 + 5, h1);
        layer_step<15, 5>(m1, h1, c1, s + OFF_W1, s + OFF_B1);

        // ---- layer 2 : D=10, U=7 padded to 8 (4 pairs), rows = 17 ----
        u64 m2[17];
        dup_from_pairs<5>(m2, h1);
        dup_from_pairs<3>(m2 + 10, h2);            // units 0..5
        { float a, b; unpack2(h2[3], a, b); m2[16] = dup2(a); (void)b; } // unit 6
        layer_step<17, 4>(m2, h2, c2, s + OFF_W2, s + OFF_B2);

        // ---- layer 3 : D=7, U=4 (2 pairs), rows = 11 ----
        u64 m3[11];
        dup_from_pairs<3>(m3, h2);
        { float a, b; unpack2(h2[3], a, b); m3[6] = dup2(a); (void)b; }
        dup_from_pairs<2>(m3 + 7, h3);
        layer_step<11, 2>(m3, h3, c3, s + OFF_W3, s + OFF_B3);

        // ---- dense 4x4 + sigmoid ----
        ulonglong2 bdv = *(const ulonglong2*)(s + OFF_BD);
        u64 z0 = bdv.x, z1 = bdv.y;
        float hs0, hs1, hs2, hs3;
        unpack2(h3[0], hs0, hs1);
        unpack2(h3[1], hs2, hs3);
        float hsv[4] = {hs0, hs1, hs2, hs3};
#pragma unroll
        for (int k = 0; k < 4; k++) {
            u64 m = dup2(hsv[k]);
            ulonglong2 w = *(const ulonglong2*)(s + OFF_WD + k * 4);
            z0 = ffma2(m, w.x, z0);
            z1 = ffma2(m, w.y, z1);
        }
        u64 r0 = sigmoid2(z0), r1 = sigmoid2(z1);
        float o0, o1, o2, o3;
        unpack2(r0, o0, o1);
        unpack2(r1, o2, o3);
        *(float4*)(op) = make_float4(o0, o1, o2, o3);
        op += NOUT;
    }
}

extern "C" void kernel_launch(void* const* d_in, const int* in_sizes, int n_in,
                              void* d_out, int out_size) {
    const float* x   = (const float*)d_in[0];
    const float* Wk1 = (const float*)d_in[1];
    const float* Wr1 = (const float*)d_in[2];
    const float* b1  = (const float*)d_in[3];
    const float* Wk2 = (const float*)d_in[4];
    const float* Wr2 = (const float*)d_in[5];
    const float* b2  = (const float*)d_in[6];
    const float* Wk3 = (const float*)d_in[7];
    const float* Wr3 = (const float*)d_in[8];
    const float* b3  = (const float*)d_in[9];
    const float* Wd  = (const float*)d_in[10];
    const float* bd  = (const float*)d_in[11];

    dim3 tgrid((SEQ * FEAT + 31) / 32, NBATCH / 32);
    transpose_kernel<<<tgrid, dim3(32, 32)>>>(x);

    lstm3_kernel<<<NBATCH / NTHREADS, NTHREADS>>>(Wk1, Wr1, b1, Wk2, Wr2, b2,
                                                  Wk3, Wr3, b3, Wd, bd, (float*)d_out);
}